// round 11
// baseline (speedup 1.0000x reference)
#include <cuda_runtime.h>
#include <cstdint>

// CostVolume1D: out[n,d,h,w] = (1/C) * sum_c f1[n,c,h,w] * f2pad[n,c,h,w+d-4]
// f1,f2: [4,128,192,640] fp32. One CTA per (n,h) row, TPB=160.
// f2: cp.async 6-stage smem pipeline (needs the +-4 float halo).
// f1: depth-2 register software prefetch via __ldg (no sharing -> no smem).

#define Nn     4
#define Cc     128
#define Hh     192
#define Ww     640
#define NS     9
#define TPB    160
#define VW     160                       // float4 per row
#define CH4    (Hh * VW)                 // channel stride in float4 units
#define STAGES 6
#define S2B    ((Ww + 8) * 4)            // 2592 B: f2 row + 4+4 float halo

__device__ __forceinline__ void cp_async16(uint32_t dst, const void* src) {
    asm volatile("cp.async.cg.shared.global [%0], [%1], 16;\n" :: "r"(dst), "l"(src));
}
__device__ __forceinline__ void cp_commit() {
    asm volatile("cp.async.commit_group;\n");
}
__device__ __forceinline__ void cp_wait() {
    asm volatile("cp.async.wait_group %0;\n" :: "n"(STAGES - 2));
}

__global__ __launch_bounds__(TPB)
void costvol1d_kernel(const float4* __restrict__ f1,
                      const float4* __restrict__ f2,
                      float* __restrict__ out)
{
    __shared__ __align__(16) char smem[STAGES * S2B];

    const int tid = threadIdx.x;            // 0..159 == float4 index v
    const int bx  = blockIdx.x;             // n*Hh + h
    const int n   = bx / Hh;
    const int h   = bx % Hh;

    uint32_t sbase;
    asm("{ .reg .u64 t; cvta.to.shared.u64 t, %1; cvt.u32.u64 %0, t; }"
        : "=r"(sbase) : "l"(smem));

    // Zero the 16B halos (front+back) of every stage's f2 row once.
    // cp.async only ever writes [16, 16+2560) within a slot.
    if (tid < STAGES * 2) {
        const int s    = tid >> 1;
        const int back = tid & 1;
        float4* p = (float4*)(smem + s * S2B + (back ? (S2B - 16) : 0));
        *p = make_float4(0.f, 0.f, 0.f, 0.f);
    }

    // Row base (in float4 units); channel c row starts at rb + c*CH4.
    const size_t rb = ((size_t)n * Cc * Hh + h) * VW + tid;

    // f2 prologue: stage channels 0..STAGES-2 into slots 0..STAGES-2.
    #pragma unroll
    for (int s = 0; s < STAGES - 1; s++) {
        cp_async16(sbase + s * S2B + 16 + tid * 16, f2 + rb + (size_t)s * CH4);
        cp_commit();
    }

    // f1 register prefetch, depth 2.
    float4 a0 = __ldg(f1 + rb);
    float4 a1 = __ldg(f1 + rb + CH4);

    float acc[NS * 4];
    #pragma unroll
    for (int i = 0; i < NS * 4; i++) acc[i] = 0.0f;

    int slot  = 0;           // slot holding f2 channel c
    int islot = STAGES - 1;  // slot to fill with channel c+STAGES-1

    #pragma unroll 2
    for (int c = 0; c < Cc; c++) {
        // Issue f1 load for channel c+2 early (clamped; tail value unused).
        const int cpre = (c + 2 < Cc) ? (c + 2) : (Cc - 1);
        const float4 a2 = __ldg(f1 + rb + (size_t)cpre * CH4);

        cp_wait();           // f2 group for channel c complete (this thread)
        __syncthreads();     // visibility + prior readers of islot done

        const float4* s2p = (const float4*)(smem + slot * S2B);
        const float4 wa = s2p[tid];       // f2pad[4v-4 .. 4v-1]
        const float4 wb = s2p[tid + 1];   // f2pad[4v   .. 4v+3]
        const float4 wc = s2p[tid + 2];   // f2pad[4v+4 .. 4v+7]

        float win[12];
        win[0] = wa.x; win[1] = wa.y; win[2]  = wa.z; win[3]  = wa.w;
        win[4] = wb.x; win[5] = wb.y; win[6]  = wb.z; win[7]  = wb.w;
        win[8] = wc.x; win[9] = wc.y; win[10] = wc.z; win[11] = wc.w;

        float av[4];
        av[0] = a0.x; av[1] = a0.y; av[2] = a0.z; av[3] = a0.w;

        #pragma unroll
        for (int d = 0; d < NS; d++) {
            #pragma unroll
            for (int j = 0; j < 4; j++) {
                acc[d * 4 + j] = fmaf(av[j], win[j + d], acc[d * 4 + j]);
            }
        }

        // Refill islot with f2 channel c+STAGES-1 (its old contents, channel
        // c-1, were consumed before this iteration's barrier). Always commit
        // so the pending-group count stays uniform for cp_wait.
        const int cn = c + STAGES - 1;
        if (cn < Cc) {
            cp_async16(sbase + islot * S2B + 16 + tid * 16,
                       f2 + rb + (size_t)cn * CH4);
        }
        cp_commit();

        a0 = a1;
        a1 = a2;
        slot  = (slot  == STAGES - 1) ? 0 : slot + 1;
        islot = (islot == STAGES - 1) ? 0 : islot + 1;
    }

    // Epilogue: channel mean, float4 stores. out[n][d][h][4v .. 4v+3]
    const float inv = 1.0f / (float)Cc;
    float4* o4 = (float4*)out;
    #pragma unroll
    for (int d = 0; d < NS; d++) {
        float4 o;
        o.x = acc[d * 4 + 0] * inv;
        o.y = acc[d * 4 + 1] * inv;
        o.z = acc[d * 4 + 2] * inv;
        o.w = acc[d * 4 + 3] * inv;
        o4[((size_t)(n * NS + d) * Hh + h) * VW + tid] = o;
    }
}

extern "C" void kernel_launch(void* const* d_in, const int* in_sizes, int n_in,
                              void* d_out, int out_size)
{
    const float4* f1 = (const float4*)d_in[0];
    const float4* f2 = (const float4*)d_in[1];
    float* out = (float*)d_out;
    (void)in_sizes; (void)n_in; (void)out_size;

    dim3 grid(Nn * Hh);   // 768 CTAs, one per (n,h) row
    dim3 block(TPB);      // 160 threads
    costvol1d_kernel<<<grid, block>>>(f1, f2, out);
}

// round 12
// speedup vs baseline: 1.3095x; 1.3095x over previous
#include <cuda_runtime.h>
#include <cstdint>

// CostVolume1D: out[n,d,h,w] = (1/C) * sum_c f1[n,c,h,w] * f2pad[n,c,h,w+d-4]
// f1,f2: [4,128,192,640] fp32. One CTA per (n,h) row, TPB=160.
// 8-stage smem ring fed by cp.async.bulk (2 row copies + 1 expect_tx per
// channel, issued by thread 0) with per-stage mbarrier complete_tx. This
// replaces R10's 320 LDGSTS/channel with 2 bulk ops, collapsing LSU issue
// pressure. Compute: 4 LDS.128 + 36 FFMA per thread per channel.

#define Nn     4
#define Cc     128
#define Hh     192
#define Ww     640
#define NS     9
#define TPB    160
#define VW     160                 // float4 per row
#define CH4    (Hh * VW)           // channel stride in float4 units (30720)
#define STAGES 8
#define ROWB   2560                // one row = 160 float4 = 2560 B
#define S1B    2560                // f1 region in slot
#define S2B    2592                // f2 region: 16B halo + 2560 + 16B halo
#define SLOTB  (S1B + S2B)         // 5152 B per stage

__device__ __forceinline__ uint32_t smem_u32(const void* p) {
    uint32_t a;
    asm("{ .reg .u64 t; cvta.to.shared.u64 t, %1; cvt.u32.u64 %0, t; }"
        : "=r"(a) : "l"(p));
    return a;
}
__device__ __forceinline__ void mbar_init(uint32_t m, uint32_t cnt) {
    asm volatile("mbarrier.init.shared.b64 [%0], %1;" :: "r"(m), "r"(cnt) : "memory");
}
__device__ __forceinline__ void mbar_expect(uint32_t m, uint32_t bytes) {
    asm volatile("mbarrier.arrive.expect_tx.shared.b64 _, [%0], %1;"
                 :: "r"(m), "r"(bytes) : "memory");
}
__device__ __forceinline__ void bulk_g2s(uint32_t dst, const void* src,
                                         uint32_t bytes, uint32_t m) {
    asm volatile("cp.async.bulk.shared::cta.global.mbarrier::complete_tx::bytes "
                 "[%0], [%1], %2, [%3];"
                 :: "r"(dst), "l"(src), "r"(bytes), "r"(m) : "memory");
}
__device__ __forceinline__ void mbar_wait(uint32_t m, uint32_t ph) {
    uint32_t done;
    asm volatile(
        "{\n\t.reg .pred p;\n\t"
        "mbarrier.try_wait.parity.acquire.cta.shared::cta.b64 p, [%1], %2;\n\t"
        "selp.b32 %0, 1, 0, p;\n\t}"
        : "=r"(done) : "r"(m), "r"(ph) : "memory");
    if (!done) {
        asm volatile(
            "{\n\t.reg .pred P1;\n\t"
            "WL_%=:\n\t"
            "mbarrier.try_wait.parity.acquire.cta.shared::cta.b64 P1, [%0], %1;\n\t"
            "@P1 bra.uni WD_%=;\n\t"
            "bra.uni WL_%=;\n\t"
            "WD_%=:\n\t}"
            :: "r"(m), "r"(ph) : "memory");
    }
}

__global__ __launch_bounds__(TPB)
void costvol1d_kernel(const float4* __restrict__ f1,
                      const float4* __restrict__ f2,
                      float* __restrict__ out)
{
    __shared__ __align__(16) char buf[STAGES * SLOTB];
    __shared__ __align__(8)  uint64_t mbar[STAGES];

    const int tid = threadIdx.x;            // 0..159 == float4 index v
    const int bx  = blockIdx.x;             // n*Hh + h
    const int n   = bx / Hh;
    const int h   = bx % Hh;

    const uint32_t sbuf = smem_u32(buf);
    const uint32_t smb  = smem_u32(mbar);

    // Init mbarriers (count 1: the producer's expect_tx is the sole arrive).
    if (tid == 0) {
        #pragma unroll
        for (int s = 0; s < STAGES; s++) mbar_init(smb + s * 8, 1);
    }
    // Zero the 16B halos (front+back) of every stage's f2 region once.
    // Bulk copies only ever write [S1B+16, S1B+16+2560) within a slot.
    if (tid < STAGES * 2) {
        const int s    = tid >> 1;
        const int back = tid & 1;
        float4* p = (float4*)(buf + s * SLOTB + S1B + (back ? (S2B - 16) : 0));
        *p = make_float4(0.f, 0.f, 0.f, 0.f);
    }
    __syncthreads();   // barriers + halos visible before any bulk/consume

    // Row base (in float4 units); channel c row starts at rb + c*CH4.
    const size_t rb = ((size_t)n * Cc * Hh + h) * VW;

    // Prologue: fill stages 0..STAGES-2 with channels 0..STAGES-2.
    if (tid == 0) {
        #pragma unroll
        for (int s = 0; s < STAGES - 1; s++) {
            const uint32_t slot = sbuf + s * SLOTB;
            mbar_expect(smb + s * 8, 2 * ROWB);
            bulk_g2s(slot,             f1 + rb + (size_t)s * CH4, ROWB, smb + s * 8);
            bulk_g2s(slot + S1B + 16,  f2 + rb + (size_t)s * CH4, ROWB, smb + s * 8);
        }
    }

    float acc[NS * 4];
    #pragma unroll
    for (int i = 0; i < NS * 4; i++) acc[i] = 0.0f;

    int ss = 0;     // stage holding channel c
    int ph = 0;     // parity for that stage

    for (int c = 0; c < Cc; c++) {
        mbar_wait(smb + ss * 8, ph);

        const char* slot = buf + ss * SLOTB;
        const float4* s1p = (const float4*)(slot);
        const float4* s2p = (const float4*)(slot + S1B);

        const float4 a  = s1p[tid];
        const float4 wa = s2p[tid];       // f2pad[4v-4 .. 4v-1]
        const float4 wb = s2p[tid + 1];   // f2pad[4v   .. 4v+3]
        const float4 wc = s2p[tid + 2];   // f2pad[4v+4 .. 4v+7]

        float win[12];
        win[0] = wa.x; win[1] = wa.y; win[2]  = wa.z; win[3]  = wa.w;
        win[4] = wb.x; win[5] = wb.y; win[6]  = wb.z; win[7]  = wb.w;
        win[8] = wc.x; win[9] = wc.y; win[10] = wc.z; win[11] = wc.w;

        float av[4];
        av[0] = a.x; av[1] = a.y; av[2] = a.z; av[3] = a.w;

        #pragma unroll
        for (int d = 0; d < NS; d++) {
            #pragma unroll
            for (int j = 0; j < 4; j++) {
                acc[d * 4 + j] = fmaf(av[j], win[j + d], acc[d * 4 + j]);
            }
        }

        __syncthreads();   // all threads finished reading stage (c-1)%STAGES
                           // (and this one) before any refill overwrites it.

        // Refill: channel cn = c+STAGES-1 into stage (c-1) mod STAGES
        // (consumed at iteration c-1; ordered by the barrier above).
        const int cn = c + STAGES - 1;
        if (tid == 0 && cn < Cc) {
            const int is = (ss == 0) ? (STAGES - 1) : (ss - 1);
            const uint32_t slotw = sbuf + is * SLOTB;
            mbar_expect(smb + is * 8, 2 * ROWB);
            bulk_g2s(slotw,            f1 + rb + (size_t)cn * CH4, ROWB, smb + is * 8);
            bulk_g2s(slotw + S1B + 16, f2 + rb + (size_t)cn * CH4, ROWB, smb + is * 8);
        }

        if (++ss == STAGES) { ss = 0; ph ^= 1; }
    }

    // Epilogue: channel mean, float4 stores. out[n][d][h][4v .. 4v+3]
    const float inv = 1.0f / (float)Cc;
    float4* o4 = (float4*)out;
    #pragma unroll
    for (int d = 0; d < NS; d++) {
        float4 o;
        o.x = acc[d * 4 + 0] * inv;
        o.y = acc[d * 4 + 1] * inv;
        o.z = acc[d * 4 + 2] * inv;
        o.w = acc[d * 4 + 3] * inv;
        o4[((size_t)(n * NS + d) * Hh + h) * VW + tid] = o;
    }
}

extern "C" void kernel_launch(void* const* d_in, const int* in_sizes, int n_in,
                              void* d_out, int out_size)
{
    const float4* f1 = (const float4*)d_in[0];
    const float4* f2 = (const float4*)d_in[1];
    float* out = (float*)d_out;
    (void)in_sizes; (void)n_in; (void)out_size;

    dim3 grid(Nn * Hh);   // 768 CTAs, one per (n,h) row
    dim3 block(TPB);      // 160 threads
    costvol1d_kernel<<<grid, block>>>(f1, f2, out);
}

// round 13
// speedup vs baseline: 1.5000x; 1.1455x over previous
#include <cuda_runtime.h>
#include <cstdint>

// CostVolume1D: out[n,d,h,w] = (1/C) * sum_c f1[n,c,h,w] * f2pad[n,c,h,w+d-4]
// f1,f2: [4,128,192,640] fp32. One CTA per (n,h) row, TPB=160.
// 7-stage smem ring fed by cp.async.bulk + mbarrier complete_tx (2 bulk row
// copies per channel from thread 0). STAGES=7 + launch_bounds(160,6) keeps
// smem at 35.3KB and regs ~61 so SIX CTAs fit per SM: 148*6=888 >= 768 grid
// -> ALL CTAs resident from t=0, no straggler tail (the tail is what capped
// the previous champions at ~5.5 TB/s average).

#define Nn     4
#define Cc     128
#define Hh     192
#define Ww     640
#define NS     9
#define TPB    160
#define VW     160                 // float4 per row
#define CH4    (Hh * VW)           // channel stride in float4 units (30720)
#define STAGES 7
#define ROWB   2560                // one row = 160 float4 = 2560 B
#define S1B    2560                // f1 region in slot
#define S2B    2592                // f2 region: 16B halo + 2560 + 16B halo
#define SLOTB  (S1B + S2B)         // 5152 B per stage

__device__ __forceinline__ uint32_t smem_u32(const void* p) {
    uint32_t a;
    asm("{ .reg .u64 t; cvta.to.shared.u64 t, %1; cvt.u32.u64 %0, t; }"
        : "=r"(a) : "l"(p));
    return a;
}
__device__ __forceinline__ void mbar_init(uint32_t m, uint32_t cnt) {
    asm volatile("mbarrier.init.shared.b64 [%0], %1;" :: "r"(m), "r"(cnt) : "memory");
}
__device__ __forceinline__ void mbar_expect(uint32_t m, uint32_t bytes) {
    asm volatile("mbarrier.arrive.expect_tx.shared.b64 _, [%0], %1;"
                 :: "r"(m), "r"(bytes) : "memory");
}
__device__ __forceinline__ void bulk_g2s(uint32_t dst, const void* src,
                                         uint32_t bytes, uint32_t m) {
    asm volatile("cp.async.bulk.shared::cta.global.mbarrier::complete_tx::bytes "
                 "[%0], [%1], %2, [%3];"
                 :: "r"(dst), "l"(src), "r"(bytes), "r"(m) : "memory");
}
__device__ __forceinline__ void mbar_wait(uint32_t m, uint32_t ph) {
    uint32_t done;
    asm volatile(
        "{\n\t.reg .pred p;\n\t"
        "mbarrier.try_wait.parity.acquire.cta.shared::cta.b64 p, [%1], %2;\n\t"
        "selp.b32 %0, 1, 0, p;\n\t}"
        : "=r"(done) : "r"(m), "r"(ph) : "memory");
    if (!done) {
        asm volatile(
            "{\n\t.reg .pred P1;\n\t"
            "WL_%=:\n\t"
            "mbarrier.try_wait.parity.acquire.cta.shared::cta.b64 P1, [%0], %1;\n\t"
            "@P1 bra.uni WD_%=;\n\t"
            "bra.uni WL_%=;\n\t"
            "WD_%=:\n\t}"
            :: "r"(m), "r"(ph) : "memory");
    }
}

__global__ __launch_bounds__(TPB, 6)
void costvol1d_kernel(const float4* __restrict__ f1,
                      const float4* __restrict__ f2,
                      float* __restrict__ out)
{
    __shared__ __align__(16) char buf[STAGES * SLOTB];
    __shared__ __align__(8)  uint64_t mbar[STAGES];

    const int tid = threadIdx.x;            // 0..159 == float4 index v
    const int bx  = blockIdx.x;             // n*Hh + h
    const int n   = bx / Hh;
    const int h   = bx % Hh;

    const uint32_t sbuf = smem_u32(buf);
    const uint32_t smb  = smem_u32(mbar);

    // Init mbarriers (count 1: the producer's expect_tx is the sole arrive).
    if (tid == 0) {
        #pragma unroll
        for (int s = 0; s < STAGES; s++) mbar_init(smb + s * 8, 1);
    }
    // Zero the 16B halos (front+back) of every stage's f2 region once.
    // Bulk copies only ever write [S1B+16, S1B+16+2560) within a slot.
    if (tid < STAGES * 2) {
        const int s    = tid >> 1;
        const int back = tid & 1;
        float4* p = (float4*)(buf + s * SLOTB + S1B + (back ? (S2B - 16) : 0));
        *p = make_float4(0.f, 0.f, 0.f, 0.f);
    }
    __syncthreads();   // barriers + halos visible before any bulk/consume

    // Row base (in float4 units); channel c row starts at rb + c*CH4.
    const size_t rb = ((size_t)n * Cc * Hh + h) * VW;

    // Prologue: fill stages 0..STAGES-2 with channels 0..STAGES-2.
    if (tid == 0) {
        #pragma unroll
        for (int s = 0; s < STAGES - 1; s++) {
            const uint32_t slot = sbuf + s * SLOTB;
            mbar_expect(smb + s * 8, 2 * ROWB);
            bulk_g2s(slot,             f1 + rb + (size_t)s * CH4, ROWB, smb + s * 8);
            bulk_g2s(slot + S1B + 16,  f2 + rb + (size_t)s * CH4, ROWB, smb + s * 8);
        }
    }

    float acc[NS * 4];
    #pragma unroll
    for (int i = 0; i < NS * 4; i++) acc[i] = 0.0f;

    int ss = 0;     // stage holding channel c
    int ph = 0;     // parity for that stage

    for (int c = 0; c < Cc; c++) {
        mbar_wait(smb + ss * 8, ph);

        const char* slot = buf + ss * SLOTB;
        const float4* s1p = (const float4*)(slot);
        const float4* s2p = (const float4*)(slot + S1B);

        const float4 a  = s1p[tid];
        const float4 wa = s2p[tid];       // f2pad[4v-4 .. 4v-1]
        const float4 wb = s2p[tid + 1];   // f2pad[4v   .. 4v+3]
        const float4 wc = s2p[tid + 2];   // f2pad[4v+4 .. 4v+7]

        float win[12];
        win[0] = wa.x; win[1] = wa.y; win[2]  = wa.z; win[3]  = wa.w;
        win[4] = wb.x; win[5] = wb.y; win[6]  = wb.z; win[7]  = wb.w;
        win[8] = wc.x; win[9] = wc.y; win[10] = wc.z; win[11] = wc.w;

        float av[4];
        av[0] = a.x; av[1] = a.y; av[2] = a.z; av[3] = a.w;

        #pragma unroll
        for (int d = 0; d < NS; d++) {
            #pragma unroll
            for (int j = 0; j < 4; j++) {
                acc[d * 4 + j] = fmaf(av[j], win[j + d], acc[d * 4 + j]);
            }
        }

        __syncthreads();   // all threads finished reading stage (c-1)%STAGES
                           // (and this one) before any refill overwrites it.

        // Refill: channel cn = c+STAGES-1 into stage (c-1) mod STAGES
        // (consumed at iteration c-1; ordered by the barrier above).
        const int cn = c + STAGES - 1;
        if (tid == 0 && cn < Cc) {
            const int is = (ss == 0) ? (STAGES - 1) : (ss - 1);
            const uint32_t slotw = sbuf + is * SLOTB;
            mbar_expect(smb + is * 8, 2 * ROWB);
            bulk_g2s(slotw,            f1 + rb + (size_t)cn * CH4, ROWB, smb + is * 8);
            bulk_g2s(slotw + S1B + 16, f2 + rb + (size_t)cn * CH4, ROWB, smb + is * 8);
        }

        if (++ss == STAGES) { ss = 0; ph ^= 1; }
    }

    // Epilogue: channel mean, float4 stores. out[n][d][h][4v .. 4v+3]
    const float inv = 1.0f / (float)Cc;
    float4* o4 = (float4*)out;
    #pragma unroll
    for (int d = 0; d < NS; d++) {
        float4 o;
        o.x = acc[d * 4 + 0] * inv;
        o.y = acc[d * 4 + 1] * inv;
        o.z = acc[d * 4 + 2] * inv;
        o.w = acc[d * 4 + 3] * inv;
        o4[((size_t)(n * NS + d) * Hh + h) * VW + tid] = o;
    }
}

extern "C" void kernel_launch(void* const* d_in, const int* in_sizes, int n_in,
                              void* d_out, int out_size)
{
    const float4* f1 = (const float4*)d_in[0];
    const float4* f2 = (const float4*)d_in[1];
    float* out = (float*)d_out;
    (void)in_sizes; (void)n_in; (void)out_size;

    dim3 grid(Nn * Hh);   // 768 CTAs, one per (n,h) row — all resident at occ 6
    dim3 block(TPB);      // 160 threads
    costvol1d_kernel<<<grid, block>>>(f1, f2, out);
}

// round 14
// speedup vs baseline: 1.5457x; 1.0304x over previous
#include <cuda_runtime.h>
#include <cstdint>

// CostVolume1D: out[n,d,h,w] = (1/C) * sum_c f1[n,c,h,w] * f2pad[n,c,h,w+d-4]
// f1,f2: [4,128,192,640] fp32. One CTA per (n,h) row, TPB=160, full residency
// (6 CTAs/SM, 768 <= 888 slots -> no tail; that gave the R13 win).
// R14: paired channels on a 6-stage cp.async.bulk ring — 2 channels per
// iteration, ONE mbar-wait pair + ONE __syncthreads per 2 channels (sync
// count 128 -> 64), refill issued right after the wait (before compute).

#define Nn     4
#define Cc     128
#define Hh     192
#define Ww     640
#define NS     9
#define TPB    160
#define VW     160                 // float4 per row
#define CH4    (Hh * VW)           // channel stride in float4 units (30720)
#define STAGES 6
#define ROWB   2560                // one row = 160 float4 = 2560 B
#define S1B    2560                // f1 region in slot
#define S2B    2592                // f2 region: 16B halo + 2560 + 16B halo
#define SLOTB  (S1B + S2B)         // 5152 B per stage

__device__ __forceinline__ uint32_t smem_u32(const void* p) {
    uint32_t a;
    asm("{ .reg .u64 t; cvta.to.shared.u64 t, %1; cvt.u32.u64 %0, t; }"
        : "=r"(a) : "l"(p));
    return a;
}
__device__ __forceinline__ void mbar_init(uint32_t m, uint32_t cnt) {
    asm volatile("mbarrier.init.shared.b64 [%0], %1;" :: "r"(m), "r"(cnt) : "memory");
}
__device__ __forceinline__ void mbar_expect(uint32_t m, uint32_t bytes) {
    asm volatile("mbarrier.arrive.expect_tx.shared.b64 _, [%0], %1;"
                 :: "r"(m), "r"(bytes) : "memory");
}
__device__ __forceinline__ void bulk_g2s(uint32_t dst, const void* src,
                                         uint32_t bytes, uint32_t m) {
    asm volatile("cp.async.bulk.shared::cta.global.mbarrier::complete_tx::bytes "
                 "[%0], [%1], %2, [%3];"
                 :: "r"(dst), "l"(src), "r"(bytes), "r"(m) : "memory");
}
__device__ __forceinline__ void mbar_wait(uint32_t m, uint32_t ph) {
    uint32_t done;
    asm volatile(
        "{\n\t.reg .pred p;\n\t"
        "mbarrier.try_wait.parity.acquire.cta.shared::cta.b64 p, [%1], %2;\n\t"
        "selp.b32 %0, 1, 0, p;\n\t}"
        : "=r"(done) : "r"(m), "r"(ph) : "memory");
    if (!done) {
        asm volatile(
            "{\n\t.reg .pred P1;\n\t"
            "WL_%=:\n\t"
            "mbarrier.try_wait.parity.acquire.cta.shared::cta.b64 P1, [%0], %1;\n\t"
            "@P1 bra.uni WD_%=;\n\t"
            "bra.uni WL_%=;\n\t"
            "WD_%=:\n\t}"
            :: "r"(m), "r"(ph) : "memory");
    }
}

__global__ __launch_bounds__(TPB, 6)
void costvol1d_kernel(const float4* __restrict__ f1,
                      const float4* __restrict__ f2,
                      float* __restrict__ out)
{
    __shared__ __align__(16) char buf[STAGES * SLOTB];
    __shared__ __align__(8)  uint64_t mbar[STAGES];

    const int tid = threadIdx.x;            // 0..159 == float4 index v
    const int bx  = blockIdx.x;             // n*Hh + h
    const int n   = bx / Hh;
    const int h   = bx % Hh;

    const uint32_t sbuf = smem_u32(buf);
    const uint32_t smb  = smem_u32(mbar);

    if (tid == 0) {
        #pragma unroll
        for (int s = 0; s < STAGES; s++) mbar_init(smb + s * 8, 1);
    }
    // Zero the 16B halos (front+back) of every stage's f2 region once.
    // Bulk copies only ever write [S1B+16, S1B+16+2560) within a slot.
    if (tid < STAGES * 2) {
        const int s    = tid >> 1;
        const int back = tid & 1;
        float4* p = (float4*)(buf + s * SLOTB + S1B + (back ? (S2B - 16) : 0));
        *p = make_float4(0.f, 0.f, 0.f, 0.f);
    }
    __syncthreads();   // barriers + halos visible before any bulk/consume

    // Row base (in float4 units); channel c row starts at rb + c*CH4.
    const size_t rb = ((size_t)n * Cc * Hh + h) * VW;

    // Prologue: channels 0..3 into stages 0..3 (channel c lives in stage c%6).
    if (tid == 0) {
        #pragma unroll
        for (int s = 0; s < 4; s++) {
            const uint32_t slot = sbuf + s * SLOTB;
            mbar_expect(smb + s * 8, 2 * ROWB);
            bulk_g2s(slot,             f1 + rb + (size_t)s * CH4, ROWB, smb + s * 8);
            bulk_g2s(slot + S1B + 16,  f2 + rb + (size_t)s * CH4, ROWB, smb + s * 8);
        }
    }

    float acc[NS * 4];
    #pragma unroll
    for (int i = 0; i < NS * 4; i++) acc[i] = 0.0f;

    int ss = 0;     // stage of channel c (c even; pair = stages ss, ss+1)
    int ph = 0;     // parity for this reuse round of the ring

    for (int c = 0; c < Cc; c += 2) {
        // Wait for the pair (channels c, c+1).
        mbar_wait(smb + ss * 8, ph);
        mbar_wait(smb + (ss + 1) * 8, ph);

        // Refill EARLY: channels c+4, c+5 into stages (ss+4)%6, (ss+5)%6.
        // Those stages held channels c-2, c-1, consumed last iteration and
        // protected by last iteration's __syncthreads (skew <= 1 iteration).
        if (tid == 0 && c + 4 < Cc) {
            const int s4 = (ss + 4 < STAGES) ? (ss + 4) : (ss - 2);
            const int s5 = (ss + 5 < STAGES) ? (ss + 5) : (ss - 1);
            const uint32_t w4 = sbuf + s4 * SLOTB;
            const uint32_t w5 = sbuf + s5 * SLOTB;
            mbar_expect(smb + s4 * 8, 2 * ROWB);
            bulk_g2s(w4,            f1 + rb + (size_t)(c + 4) * CH4, ROWB, smb + s4 * 8);
            bulk_g2s(w4 + S1B + 16, f2 + rb + (size_t)(c + 4) * CH4, ROWB, smb + s4 * 8);
            mbar_expect(smb + s5 * 8, 2 * ROWB);
            bulk_g2s(w5,            f1 + rb + (size_t)(c + 5) * CH4, ROWB, smb + s5 * 8);
            bulk_g2s(w5 + S1B + 16, f2 + rb + (size_t)(c + 5) * CH4, ROWB, smb + s5 * 8);
        }

        // Consume both channels of the pair.
        #pragma unroll
        for (int u = 0; u < 2; u++) {
            const char* slot = buf + (ss + u) * SLOTB;
            const float4* s1p = (const float4*)(slot);
            const float4* s2p = (const float4*)(slot + S1B);

            const float4 a  = s1p[tid];
            const float4 wa = s2p[tid];       // f2pad[4v-4 .. 4v-1]
            const float4 wb = s2p[tid + 1];   // f2pad[4v   .. 4v+3]
            const float4 wc = s2p[tid + 2];   // f2pad[4v+4 .. 4v+7]

            float win[12];
            win[0] = wa.x; win[1] = wa.y; win[2]  = wa.z; win[3]  = wa.w;
            win[4] = wb.x; win[5] = wb.y; win[6]  = wb.z; win[7]  = wb.w;
            win[8] = wc.x; win[9] = wc.y; win[10] = wc.z; win[11] = wc.w;

            float av[4];
            av[0] = a.x; av[1] = a.y; av[2] = a.z; av[3] = a.w;

            #pragma unroll
            for (int d = 0; d < NS; d++) {
                #pragma unroll
                for (int j = 0; j < 4; j++) {
                    acc[d * 4 + j] = fmaf(av[j], win[j + d], acc[d * 4 + j]);
                }
            }
        }

        __syncthreads();   // all threads done with this pair before it can be
                           // overwritten by the refill two channels from now.

        ss += 2;
        if (ss == STAGES) { ss = 0; ph ^= 1; }
    }

    // Epilogue: channel mean, float4 stores. out[n][d][h][4v .. 4v+3]
    const float inv = 1.0f / (float)Cc;
    float4* o4 = (float4*)out;
    #pragma unroll
    for (int d = 0; d < NS; d++) {
        float4 o;
        o.x = acc[d * 4 + 0] * inv;
        o.y = acc[d * 4 + 1] * inv;
        o.z = acc[d * 4 + 2] * inv;
        o.w = acc[d * 4 + 3] * inv;
        o4[((size_t)(n * NS + d) * Hh + h) * VW + tid] = o;
    }
}

extern "C" void kernel_launch(void* const* d_in, const int* in_sizes, int n_in,
                              void* d_out, int out_size)
{
    const float4* f1 = (const float4*)d_in[0];
    const float4* f2 = (const float4*)d_in[1];
    float* out = (float*)d_out;
    (void)in_sizes; (void)n_in; (void)out_size;

    dim3 grid(Nn * Hh);   // 768 CTAs, one per (n,h) row — all resident at occ 6
    dim3 block(TPB);      // 160 threads
    costvol1d_kernel<<<grid, block>>>(f1, f2, out);
}

// round 15
// speedup vs baseline: 1.5463x; 1.0004x over previous
#include <cuda_runtime.h>
#include <cstdint>

// CostVolume1D: out[n,d,h,w] = (1/C) * sum_c f1[n,c,h,w] * f2pad[n,c,h,w+d-4]
// f1,f2: [4,128,192,640] fp32. One CTA per (n,h) row, TPB=160, full residency
// (6 CTAs/SM, 768 <= 888 slots -> no tail). Paired channels on a 6-stage
// cp.async.bulk ring. R15: ONE mbarrier per stage-PAIR (3 barriers,
// expect_tx = 4*ROWB covers all 4 bulk copies of the pair) -> one try_wait
// per iteration instead of two.

#define Nn     4
#define Cc     128
#define Hh     192
#define Ww     640
#define NS     9
#define TPB    160
#define VW     160                 // float4 per row
#define CH4    (Hh * VW)           // channel stride in float4 units (30720)
#define STAGES 6
#define NPAIR  3                   // stage pairs (one mbarrier each)
#define ROWB   2560                // one row = 160 float4 = 2560 B
#define S1B    2560                // f1 region in slot
#define S2B    2592                // f2 region: 16B halo + 2560 + 16B halo
#define SLOTB  (S1B + S2B)         // 5152 B per stage

__device__ __forceinline__ uint32_t smem_u32(const void* p) {
    uint32_t a;
    asm("{ .reg .u64 t; cvta.to.shared.u64 t, %1; cvt.u32.u64 %0, t; }"
        : "=r"(a) : "l"(p));
    return a;
}
__device__ __forceinline__ void mbar_init(uint32_t m, uint32_t cnt) {
    asm volatile("mbarrier.init.shared.b64 [%0], %1;" :: "r"(m), "r"(cnt) : "memory");
}
__device__ __forceinline__ void mbar_expect(uint32_t m, uint32_t bytes) {
    asm volatile("mbarrier.arrive.expect_tx.shared.b64 _, [%0], %1;"
                 :: "r"(m), "r"(bytes) : "memory");
}
__device__ __forceinline__ void bulk_g2s(uint32_t dst, const void* src,
                                         uint32_t bytes, uint32_t m) {
    asm volatile("cp.async.bulk.shared::cta.global.mbarrier::complete_tx::bytes "
                 "[%0], [%1], %2, [%3];"
                 :: "r"(dst), "l"(src), "r"(bytes), "r"(m) : "memory");
}
__device__ __forceinline__ void mbar_wait(uint32_t m, uint32_t ph) {
    uint32_t done;
    asm volatile(
        "{\n\t.reg .pred p;\n\t"
        "mbarrier.try_wait.parity.acquire.cta.shared::cta.b64 p, [%1], %2;\n\t"
        "selp.b32 %0, 1, 0, p;\n\t}"
        : "=r"(done) : "r"(m), "r"(ph) : "memory");
    if (!done) {
        asm volatile(
            "{\n\t.reg .pred P1;\n\t"
            "WL_%=:\n\t"
            "mbarrier.try_wait.parity.acquire.cta.shared::cta.b64 P1, [%0], %1;\n\t"
            "@P1 bra.uni WD_%=;\n\t"
            "bra.uni WL_%=;\n\t"
            "WD_%=:\n\t}"
            :: "r"(m), "r"(ph) : "memory");
    }
}

__global__ __launch_bounds__(TPB, 6)
void costvol1d_kernel(const float4* __restrict__ f1,
                      const float4* __restrict__ f2,
                      float* __restrict__ out)
{
    __shared__ __align__(16) char buf[STAGES * SLOTB];
    __shared__ __align__(8)  uint64_t mbar[NPAIR];

    const int tid = threadIdx.x;            // 0..159 == float4 index v
    const int bx  = blockIdx.x;             // n*Hh + h
    const int n   = bx / Hh;
    const int h   = bx % Hh;

    const uint32_t sbuf = smem_u32(buf);
    const uint32_t smb  = smem_u32(mbar);

    if (tid == 0) {
        #pragma unroll
        for (int s = 0; s < NPAIR; s++) mbar_init(smb + s * 8, 1);
    }
    // Zero the 16B halos (front+back) of every stage's f2 region once.
    // Bulk copies only ever write [S1B+16, S1B+16+2560) within a slot.
    if (tid < STAGES * 2) {
        const int s    = tid >> 1;
        const int back = tid & 1;
        float4* p = (float4*)(buf + s * SLOTB + S1B + (back ? (S2B - 16) : 0));
        *p = make_float4(0.f, 0.f, 0.f, 0.f);
    }
    __syncthreads();   // barriers + halos visible before any bulk/consume

    // Row base (in float4 units); channel c row starts at rb + c*CH4.
    const size_t rb = ((size_t)n * Cc * Hh + h) * VW;

    // Prologue: channels 0..3 into stages 0..3 (pairs 0 and 1).
    if (tid == 0) {
        #pragma unroll
        for (int p = 0; p < 2; p++) {
            mbar_expect(smb + p * 8, 4 * ROWB);
            #pragma unroll
            for (int u = 0; u < 2; u++) {
                const int s = p * 2 + u;   // stage = channel for prologue
                const uint32_t slot = sbuf + s * SLOTB;
                bulk_g2s(slot,            f1 + rb + (size_t)s * CH4, ROWB, smb + p * 8);
                bulk_g2s(slot + S1B + 16, f2 + rb + (size_t)s * CH4, ROWB, smb + p * 8);
            }
        }
    }

    float acc[NS * 4];
    #pragma unroll
    for (int i = 0; i < NS * 4; i++) acc[i] = 0.0f;

    int pp = 0;     // pair holding channels (c, c+1); stages 2*pp, 2*pp+1
    int ph = 0;     // parity: pair p is reused every NPAIR iterations

    for (int c = 0; c < Cc; c += 2) {
        // One wait covers both channels of the pair (4 bulk copies).
        mbar_wait(smb + pp * 8, ph);

        // Refill EARLY: channels c+4, c+5 into the pair consumed LAST
        // iteration (pair (pp+2)%3), protected by last iteration's
        // __syncthreads (skew <= 1 iteration).
        if (tid == 0 && c + 4 < Cc) {
            const int rp = (pp + 2 < NPAIR) ? (pp + 2) : (pp - 1);
            mbar_expect(smb + rp * 8, 4 * ROWB);
            #pragma unroll
            for (int u = 0; u < 2; u++) {
                const uint32_t w = sbuf + (rp * 2 + u) * SLOTB;
                const size_t cc = (size_t)(c + 4 + u) * CH4;
                bulk_g2s(w,            f1 + rb + cc, ROWB, smb + rp * 8);
                bulk_g2s(w + S1B + 16, f2 + rb + cc, ROWB, smb + rp * 8);
            }
        }

        // Consume both channels of the pair.
        #pragma unroll
        for (int u = 0; u < 2; u++) {
            const char* slot = buf + (pp * 2 + u) * SLOTB;
            const float4* s1p = (const float4*)(slot);
            const float4* s2p = (const float4*)(slot + S1B);

            const float4 a  = s1p[tid];
            const float4 wa = s2p[tid];       // f2pad[4v-4 .. 4v-1]
            const float4 wb = s2p[tid + 1];   // f2pad[4v   .. 4v+3]
            const float4 wc = s2p[tid + 2];   // f2pad[4v+4 .. 4v+7]

            float win[12];
            win[0] = wa.x; win[1] = wa.y; win[2]  = wa.z; win[3]  = wa.w;
            win[4] = wb.x; win[5] = wb.y; win[6]  = wb.z; win[7]  = wb.w;
            win[8] = wc.x; win[9] = wc.y; win[10] = wc.z; win[11] = wc.w;

            float av[4];
            av[0] = a.x; av[1] = a.y; av[2] = a.z; av[3] = a.w;

            #pragma unroll
            for (int d = 0; d < NS; d++) {
                #pragma unroll
                for (int j = 0; j < 4; j++) {
                    acc[d * 4 + j] = fmaf(av[j], win[j + d], acc[d * 4 + j]);
                }
            }
        }

        __syncthreads();   // all threads done with this pair before it gets
                           // overwritten by the refill two iterations hence.

        if (++pp == NPAIR) { pp = 0; ph ^= 1; }
    }

    // Epilogue: channel mean, float4 stores. out[n][d][h][4v .. 4v+3]
    const float inv = 1.0f / (float)Cc;
    float4* o4 = (float4*)out;
    #pragma unroll
    for (int d = 0; d < NS; d++) {
        float4 o;
        o.x = acc[d * 4 + 0] * inv;
        o.y = acc[d * 4 + 1] * inv;
        o.z = acc[d * 4 + 2] * inv;
        o.w = acc[d * 4 + 3] * inv;
        o4[((size_t)(n * NS + d) * Hh + h) * VW + tid] = o;
    }
}

extern "C" void kernel_launch(void* const* d_in, const int* in_sizes, int n_in,
                              void* d_out, int out_size)
{
    const float4* f1 = (const float4*)d_in[0];
    const float4* f2 = (const float4*)d_in[1];
    float* out = (float*)d_out;
    (void)in_sizes; (void)n_in; (void)out_size;

    dim3 grid(Nn * Hh);   // 768 CTAs, one per (n,h) row — all resident at occ 6
    dim3 block(TPB);      // 160 threads
    costvol1d_kernel<<<grid, block>>>(f1, f2, out);
}